// round 1
// baseline (speedup 1.0000x reference)
#include <cuda_runtime.h>
#include <cuda_bf16.h>

#define THREADS 256

__global__ __launch_bounds__(THREADS) void snn_fused_kernel(
    const float* __restrict__ x,       // [B,T,A,D] = [2048,90,4,256]
    const float* __restrict__ w_ant,   // [4]
    const float* __restrict__ b_ant,   // scalar
    const float* __restrict__ w_hid,   // [10,256]
    const float* __restrict__ b_hid,   // [10]
    const float* __restrict__ w_time,  // [90]
    const float* __restrict__ b_time,  // scalar
    const float* __restrict__ w_out,   // [2,10]
    const float* __restrict__ b_out,   // [2]
    float* __restrict__ out)           // [B,2]
{
    __shared__ float4 s_whid4[10 * 64];   // w_hid as float4: [h][64]
    __shared__ float  s_sn[90][10];       // sn_in (pre-bias) per timestep
    __shared__ float  s_wtime[90];
    __shared__ float  s_bias[10];
    __shared__ float  s_fused[10];

    const int tid = threadIdx.x;
    const int b   = blockIdx.x;

    // ---- init: stage weights into smem ----
    const float4* wh4 = reinterpret_cast<const float4*>(w_hid);
    for (int i = tid; i < 640; i += THREADS) s_whid4[i] = wh4[i];
    if (tid < 90) s_wtime[tid] = w_time[tid];
    __syncthreads();
    if (tid < 10) {
        const float* row = reinterpret_cast<const float*>(&s_whid4[tid * 64]);
        float s = 0.f;
        #pragma unroll 8
        for (int d = 0; d < 256; ++d) s += row[d];
        s_bias[tid] = b_hid[tid] + b_ant[0] * s;   // fold conv bias into hidden bias
    }
    const float wa0 = w_ant[0], wa1 = w_ant[1], wa2 = w_ant[2], wa3 = w_ant[3];
    __syncthreads();

    const int warp = tid >> 5;
    const int lane = tid & 31;
    // per-batch base: 90*4*256 floats = 90*256 float4
    const float4* xb = reinterpret_cast<const float4*>(x) + (size_t)b * 90 * 256;

    // ---- phase 1: fused antenna-conv + hidden GEMV per timestep ----
    for (int t = warp; t < 90; t += 8) {
        const float4* xt = xb + t * 256;          // 4 antennas x 64 float4 each
        // issue all 8 loads up front (MLP=8)
        float4 a00 = xt[lane      ];
        float4 a01 = xt[lane + 32 ];
        float4 a10 = xt[lane + 64 ];
        float4 a11 = xt[lane + 96 ];
        float4 a20 = xt[lane + 128];
        float4 a21 = xt[lane + 160];
        float4 a30 = xt[lane + 192];
        float4 a31 = xt[lane + 224];

        float4 f0, f1;  // fused[d] for d4 = lane and lane+32
        f0.x = fmaf(a30.x, wa3, fmaf(a20.x, wa2, fmaf(a10.x, wa1, a00.x * wa0)));
        f0.y = fmaf(a30.y, wa3, fmaf(a20.y, wa2, fmaf(a10.y, wa1, a00.y * wa0)));
        f0.z = fmaf(a30.z, wa3, fmaf(a20.z, wa2, fmaf(a10.z, wa1, a00.z * wa0)));
        f0.w = fmaf(a30.w, wa3, fmaf(a20.w, wa2, fmaf(a10.w, wa1, a00.w * wa0)));
        f1.x = fmaf(a31.x, wa3, fmaf(a21.x, wa2, fmaf(a11.x, wa1, a01.x * wa0)));
        f1.y = fmaf(a31.y, wa3, fmaf(a21.y, wa2, fmaf(a11.y, wa1, a01.y * wa0)));
        f1.z = fmaf(a31.z, wa3, fmaf(a21.z, wa2, fmaf(a11.z, wa1, a01.z * wa0)));
        f1.w = fmaf(a31.w, wa3, fmaf(a21.w, wa2, fmaf(a11.w, wa1, a01.w * wa0)));

        float acc[10];
        #pragma unroll
        for (int h = 0; h < 10; ++h) {
            float4 w0 = s_whid4[h * 64 + lane];
            float4 w1 = s_whid4[h * 64 + lane + 32];
            float r;
            r = f0.x * w0.x;
            r = fmaf(f0.y, w0.y, r);
            r = fmaf(f0.z, w0.z, r);
            r = fmaf(f0.w, w0.w, r);
            r = fmaf(f1.x, w1.x, r);
            r = fmaf(f1.y, w1.y, r);
            r = fmaf(f1.z, w1.z, r);
            r = fmaf(f1.w, w1.w, r);
            acc[h] = r;
        }

        // warp tree-reduce each of the 10 partials to lane 0
        #pragma unroll
        for (int h = 0; h < 10; ++h) {
            #pragma unroll
            for (int off = 16; off > 0; off >>= 1)
                acc[h] += __shfl_down_sync(0xffffffffu, acc[h], off);
        }
        if (lane == 0) {
            #pragma unroll
            for (int h = 0; h < 10; ++h) s_sn[t][h] = acc[h];
        }
    }
    __syncthreads();

    // ---- phase 2: Leaky scan over T (serial, 10 lanes) + time fuse ----
    if (tid < 10) {
        const int h = tid;
        const float bias = s_bias[h];
        float mem = 0.f, acc = 0.f;
        #pragma unroll 6
        for (int t = 0; t < 90; ++t) {
            float inp = s_sn[t][h] + bias;
            // reset from PREVIOUS mem, reset_mechanism='zero'
            float mem_new = (mem > 1.0f) ? 0.0f : fmaf(0.95f, mem, inp);
            // spike: Heaviside(mem_new - 1)
            if (mem_new > 1.0f) acc += s_wtime[t];
            mem = mem_new;
        }
        s_fused[h] = acc + b_time[0];
    }
    __syncthreads();

    // ---- phase 3: output GEMV + softmax (O=2) ----
    if (tid == 0) {
        float o0 = b_out[0], o1 = b_out[1];
        #pragma unroll
        for (int h = 0; h < 10; ++h) {
            o0 = fmaf(s_fused[h], w_out[h],      o0);
            o1 = fmaf(s_fused[h], w_out[10 + h], o1);
        }
        float m  = fmaxf(o0, o1);
        float e0 = __expf(o0 - m);
        float e1 = __expf(o1 - m);
        float inv = 1.0f / (e0 + e1);
        out[2 * b]     = e0 * inv;
        out[2 * b + 1] = e1 * inv;
    }
}

extern "C" void kernel_launch(void* const* d_in, const int* in_sizes, int n_in,
                              void* d_out, int out_size) {
    const float* x      = (const float*)d_in[0];
    const float* w_ant  = (const float*)d_in[1];
    const float* b_ant  = (const float*)d_in[2];
    const float* w_hid  = (const float*)d_in[3];
    const float* b_hid  = (const float*)d_in[4];
    const float* w_time = (const float*)d_in[5];
    const float* b_time = (const float*)d_in[6];
    const float* w_out  = (const float*)d_in[7];
    const float* b_out  = (const float*)d_in[8];
    float* out = (float*)d_out;

    const int B = in_sizes[0] / (90 * 4 * 256);   // 2048
    snn_fused_kernel<<<B, THREADS>>>(x, w_ant, b_ant, w_hid, b_hid,
                                     w_time, b_time, w_out, b_out, out);
}

// round 2
// speedup vs baseline: 1.2028x; 1.2028x over previous
#include <cuda_runtime.h>
#include <cuda_bf16.h>

#define THREADS 256

// Pair-reduce: lanes with (lane & s)==0 end with full reduction of `a`,
// lanes with (lane & s)!=0 end with full reduction of `b`, over the lane
// pair {l, l^s} (given both inputs already reduced over smaller strides).
__device__ __forceinline__ float pair_reduce(float a, float b, int s, int lane) {
    bool hi = (lane & s) != 0;
    float send = hi ? a : b;                          // what my partner keeps
    float recv = __shfl_xor_sync(0xffffffffu, send, s);
    float keep = hi ? b : a;
    return keep + recv;
}

__global__ __launch_bounds__(THREADS, 3) void snn_fused_kernel(
    const float* __restrict__ x,       // [B,T,A,D] = [2048,90,4,256]
    const float* __restrict__ w_ant,   // [4]
    const float* __restrict__ b_ant,   // scalar
    const float* __restrict__ w_hid,   // [10,256]
    const float* __restrict__ b_hid,   // [10]
    const float* __restrict__ w_time,  // [90]
    const float* __restrict__ b_time,  // scalar
    const float* __restrict__ w_out,   // [2,10]
    const float* __restrict__ b_out,   // [2]
    float* __restrict__ out)           // [B,2]
{
    __shared__ float4 s_whid4[10 * 64];   // w_hid as float4: [h][64]
    __shared__ float  s_sn[90][10];       // sn_in (pre-bias) per timestep
    __shared__ float  s_wtime[90];
    __shared__ float  s_bias[10];
    __shared__ float  s_fused[10];

    const int tid = threadIdx.x;
    const int b   = blockIdx.x;

    // ---- init: stage weights into smem ----
    const float4* wh4 = reinterpret_cast<const float4*>(w_hid);
    for (int i = tid; i < 640; i += THREADS) s_whid4[i] = wh4[i];
    if (tid < 90) s_wtime[tid] = w_time[tid];
    __syncthreads();
    if (tid < 10) {
        const float* row = reinterpret_cast<const float*>(&s_whid4[tid * 64]);
        float s = 0.f;
        #pragma unroll 8
        for (int d = 0; d < 256; ++d) s += row[d];
        s_bias[tid] = b_hid[tid] + b_ant[0] * s;   // fold conv bias into hidden bias
    }
    const float wa0 = w_ant[0], wa1 = w_ant[1], wa2 = w_ant[2], wa3 = w_ant[3];
    __syncthreads();

    const int warp = tid >> 5;
    const int lane = tid & 31;
    // per-batch base: 90*4*256 floats = 90*256 float4
    const float4* xb = reinterpret_cast<const float4*>(x) + (size_t)b * 90 * 256;

    // ---- phase 1: fused antenna-conv + hidden GEMV per timestep ----
    for (int t = warp; t < 90; t += 8) {
        const float4* xt = xb + t * 256;          // 4 antennas x 64 float4 each
        // issue all 8 loads up front (MLP=8), streaming (read-once)
        float4 a00 = __ldcs(xt + lane      );
        float4 a01 = __ldcs(xt + lane + 32 );
        float4 a10 = __ldcs(xt + lane + 64 );
        float4 a11 = __ldcs(xt + lane + 96 );
        float4 a20 = __ldcs(xt + lane + 128);
        float4 a21 = __ldcs(xt + lane + 160);
        float4 a30 = __ldcs(xt + lane + 192);
        float4 a31 = __ldcs(xt + lane + 224);

        float4 f0, f1;  // fused[d] for d4 = lane and lane+32
        f0.x = fmaf(a30.x, wa3, fmaf(a20.x, wa2, fmaf(a10.x, wa1, a00.x * wa0)));
        f0.y = fmaf(a30.y, wa3, fmaf(a20.y, wa2, fmaf(a10.y, wa1, a00.y * wa0)));
        f0.z = fmaf(a30.z, wa3, fmaf(a20.z, wa2, fmaf(a10.z, wa1, a00.z * wa0)));
        f0.w = fmaf(a30.w, wa3, fmaf(a20.w, wa2, fmaf(a10.w, wa1, a00.w * wa0)));
        f1.x = fmaf(a31.x, wa3, fmaf(a21.x, wa2, fmaf(a11.x, wa1, a01.x * wa0)));
        f1.y = fmaf(a31.y, wa3, fmaf(a21.y, wa2, fmaf(a11.y, wa1, a01.y * wa0)));
        f1.z = fmaf(a31.z, wa3, fmaf(a21.z, wa2, fmaf(a11.z, wa1, a01.z * wa0)));
        f1.w = fmaf(a31.w, wa3, fmaf(a21.w, wa2, fmaf(a11.w, wa1, a01.w * wa0)));

        float acc[10];
        #pragma unroll
        for (int h = 0; h < 10; ++h) {
            float4 w0 = s_whid4[h * 64 + lane];
            float4 w1 = s_whid4[h * 64 + lane + 32];
            float r;
            r = f0.x * w0.x;
            r = fmaf(f0.y, w0.y, r);
            r = fmaf(f0.z, w0.z, r);
            r = fmaf(f0.w, w0.w, r);
            r = fmaf(f1.x, w1.x, r);
            r = fmaf(f1.y, w1.y, r);
            r = fmaf(f1.z, w1.z, r);
            r = fmaf(f1.w, w1.w, r);
            acc[h] = r;
        }

        // ---- log-packed warp reduction: 12 SHFL instead of 50 ----
        // Level s=16: pair h-values (2j, 2j+1); h bit0 <- lane bit16
        float v0 = pair_reduce(acc[0], acc[1], 16, lane);
        float v1 = pair_reduce(acc[2], acc[3], 16, lane);
        float v2 = pair_reduce(acc[4], acc[5], 16, lane);
        float v3 = pair_reduce(acc[6], acc[7], 16, lane);
        float v4 = pair_reduce(acc[8], acc[9], 16, lane);
        // Level s=8: h bit1 <- lane bit8 ; v4 (h=8|9) just reduces
        float u0 = pair_reduce(v0, v1, 8, lane);
        float u1 = pair_reduce(v2, v3, 8, lane);
        v4 += __shfl_xor_sync(0xffffffffu, v4, 8);
        // Level s=4: h bit2 <- lane bit4 ; v4 reduces
        float w0 = pair_reduce(u0, u1, 4, lane);
        v4 += __shfl_xor_sync(0xffffffffu, v4, 4);
        // Level s=2: select h<8 tree vs h>=8 tree by lane bit2
        float z = pair_reduce(w0, v4, 2, lane);
        // Level s=1: final reduce
        z += __shfl_xor_sync(0xffffffffu, z, 1);

        // lane -> h mapping and unique writer selection
        int h = (lane & 2) ? (8 + ((lane >> 4) & 1))
                           : (((lane >> 2) & 1) * 4 + ((lane >> 3) & 1) * 2 + ((lane >> 4) & 1));
        bool writer = ((lane & 1) == 0) && (((lane & 2) == 0) || ((lane & 12) == 0));
        if (writer) s_sn[t][h] = z;
    }
    __syncthreads();

    // ---- phase 2: Leaky scan over T (serial, 10 lanes) + time fuse ----
    if (tid < 10) {
        const int h = tid;
        const float bias = s_bias[h];
        float mem = 0.f, acc = 0.f;
        #pragma unroll 6
        for (int t = 0; t < 90; ++t) {
            float inp = s_sn[t][h] + bias;
            // reset from PREVIOUS mem, reset_mechanism='zero'
            float mem_new = (mem > 1.0f) ? 0.0f : fmaf(0.95f, mem, inp);
            // spike: Heaviside(mem_new - 1)
            if (mem_new > 1.0f) acc += s_wtime[t];
            mem = mem_new;
        }
        s_fused[h] = acc + b_time[0];
    }
    __syncthreads();

    // ---- phase 3: output GEMV + softmax (O=2) ----
    if (tid == 0) {
        float o0 = b_out[0], o1 = b_out[1];
        #pragma unroll
        for (int h = 0; h < 10; ++h) {
            o0 = fmaf(s_fused[h], w_out[h],      o0);
            o1 = fmaf(s_fused[h], w_out[10 + h], o1);
        }
        float m  = fmaxf(o0, o1);
        float e0 = __expf(o0 - m);
        float e1 = __expf(o1 - m);
        float inv = 1.0f / (e0 + e1);
        out[2 * b]     = e0 * inv;
        out[2 * b + 1] = e1 * inv;
    }
}

extern "C" void kernel_launch(void* const* d_in, const int* in_sizes, int n_in,
                              void* d_out, int out_size) {
    const float* x      = (const float*)d_in[0];
    const float* w_ant  = (const float*)d_in[1];
    const float* b_ant  = (const float*)d_in[2];
    const float* w_hid  = (const float*)d_in[3];
    const float* b_hid  = (const float*)d_in[4];
    const float* w_time = (const float*)d_in[5];
    const float* b_time = (const float*)d_in[6];
    const float* w_out  = (const float*)d_in[7];
    const float* b_out  = (const float*)d_in[8];
    float* out = (float*)d_out;

    const int B = in_sizes[0] / (90 * 4 * 256);   // 2048
    snn_fused_kernel<<<B, THREADS>>>(x, w_ant, b_ant, w_hid, b_hid,
                                     w_time, b_time, w_out, b_out, out);
}